// round 15
// baseline (speedup 1.0000x reference)
#include <cuda_runtime.h>
#include <cuda_bf16.h>

#define NB 32
#define NS 1024
#define ND 256

typedef unsigned long long ull;

// ---------------- packed f32x2 helpers --------------------------------------
__device__ __forceinline__ void FMA2(ull& d, ull a, ull b) {
    asm("fma.rn.f32x2 %0, %1, %2, %0;" : "+l"(d) : "l"(a), "l"(b));
}
__device__ __forceinline__ ull MUL2(ull a, ull b) {
    ull d;
    asm("mul.rn.f32x2 %0, %1, %2;" : "=l"(d) : "l"(a), "l"(b));
    return d;
}
__device__ __forceinline__ ull splat2(float v) {
    ull r;
    asm("mov.b64 %0, {%1, %1};" : "=l"(r) : "f"(v));
    return r;
}
__device__ __forceinline__ ull pack2(float x, float y) {
    ull r;
    asm("mov.b64 %0, {%1, %2};" : "=l"(r) : "f"(x), "f"(y));
    return r;
}
__device__ __forceinline__ float2 u2f(ull v) {
    float2 r;
    asm("mov.b64 {%0, %1}, %2;" : "=f"(r.x), "=f"(r.y) : "l"(v));
    return r;
}

// ---------------- scratch (static __device__, no allocation) ----------------
__device__ __align__(16) float g_M[ND][ND];     // M[d][e] = sum_a Wq[a][d]*Wk[a][e]
__device__ __align__(16) float g_vecA[ND];      // Wq^T bk
__device__ __align__(16) float g_vecB[ND];      // Wk^T bq
__device__ float g_c;                           // bq . bk
__device__ int   g_sw_idx[NB][NS];
__device__ int   g_dr_idx[NB][NS];
__device__ int   g_nsw[NB];
__device__ int   g_ndr[NB];
__device__ int   g_swf[NB * NS];                // 1 iff switch row
__device__ __align__(16) float g_partAll[NB][4][ND];
__device__ __align__(16) float g_partDoor[NB][4][ND];
__device__ __align__(16) float g_pz[2][NB][NS][ND];     // K-split z partials (no cw)
// split-KV partials, indexed by switch SLOT
__device__ __align__(16) float g_pm[NB][4][NS];
__device__ __align__(16) float g_pd[NB][4][NS];
__device__ __align__(16) float g_pacc[NB][4][NS][ND];

// ---------------- K_M: M = Wq^T Wk (32x32 tiles) + bias vectors + c ---------
__global__ void __launch_bounds__(256) k_M(const float* __restrict__ Wq,
                                           const float* __restrict__ Wk,
                                           const float* __restrict__ bq,
                                           const float* __restrict__ bk) {
    int tid = threadIdx.x;
    if (blockIdx.x == 64) {
        int d = tid;
        float va = 0.f, vb = 0.f;
        #pragma unroll 8
        for (int a = 0; a < ND; a++) {
            va += Wq[a * ND + d] * bk[a];
            vb += Wk[a * ND + d] * bq[a];
        }
        g_vecA[d] = va;
        g_vecB[d] = vb;
        if (tid < 32) {
            float c = 0.f;
            for (int i = tid; i < ND; i += 32) c += bq[i] * bk[i];
            #pragma unroll
            for (int o = 16; o; o >>= 1) c += __shfl_down_sync(0xFFFFFFFFu, c, o);
            if (tid == 0) g_c = c;
        }
        return;
    }
    int dt = blockIdx.x >> 3, et = blockIdx.x & 7;
    __shared__ float As[16][32], Bs[16][32];
    float a00 = 0.f, a01 = 0.f, a10 = 0.f, a11 = 0.f;
    int dg = tid >> 4, eg = tid & 15;
    int al = tid >> 4, c2 = (tid & 15) * 2;
    for (int a0 = 0; a0 < ND; a0 += 16) {
        *(float2*)&As[al][c2] = *(const float2*)&Wq[(a0 + al) * ND + dt * 32 + c2];
        *(float2*)&Bs[al][c2] = *(const float2*)&Wk[(a0 + al) * ND + et * 32 + c2];
        __syncthreads();
        #pragma unroll
        for (int k = 0; k < 16; k++) {
            float2 av = *(const float2*)&As[k][dg * 2];
            float2 bv = *(const float2*)&Bs[k][eg * 2];
            a00 += av.x * bv.x; a01 += av.x * bv.y;
            a10 += av.y * bv.x; a11 += av.y * bv.y;
        }
        __syncthreads();
    }
    int d = dt * 32 + dg * 2, e = et * 32 + eg * 2;
    g_M[d][e]     = a00; g_M[d][e + 1]     = a01;
    g_M[d + 1][e] = a10; g_M[d + 1][e + 1] = a11;
}

// ---------------- K_prep2: dtype detect + masks/flags (bz0) | colsum --------
__global__ void __launch_bounds__(1024) k_prep2(const int* __restrict__ s32,
                                                const float* __restrict__ emb) {
    int b = blockIdx.x, bz = blockIdx.y, tid = threadIdx.x;
    int vdet = (tid < 512) ? s32[b * NS + 2 * tid + 1] : 0;
    int is64 = !__syncthreads_or(vdet != 0);

    if (bz == 0) {
        int t = tid;
        int st = is64 ? s32[2 * (b * NS + t)] : s32[b * NS + t];
        int isw = (st == 3), idr = (st == 4 || st == 5);
        g_swf[b * NS + t] = isw;
        unsigned mw = __ballot_sync(0xFFFFFFFFu, isw);
        unsigned md = __ballot_sync(0xFFFFFFFFu, idr);
        int lane = t & 31, w = t >> 5;
        __shared__ int cw_[32], cd_[32], ow_[32], od_[32];
        if (lane == 0) { cw_[w] = __popc(mw); cd_[w] = __popc(md); }
        __syncthreads();
        if (tid == 0) {
            int aw = 0, ad = 0;
            for (int i = 0; i < 32; i++) {
                ow_[i] = aw; aw += cw_[i];
                od_[i] = ad; ad += cd_[i];
            }
            g_nsw[b] = aw; g_ndr[b] = ad;
        }
        __syncthreads();
        if (isw) g_sw_idx[b][ow_[w] + __popc(mw & ((1u << lane) - 1u))] = t;
        if (idr) g_dr_idx[b][od_[w] + __popc(md & ((1u << lane) - 1u))] = t;
    } else {
        int c = bz - 1, tg = tid >> 8, d = tid & 255;
        float sa = 0.f, sd = 0.f;
        int tb = c * 256 + tg * 64;
        #pragma unroll 4
        for (int i = 0; i < 64; i++) {
            int t = tb + i;
            float v = emb[((size_t)b * NS + t) * ND + d];
            int st = is64 ? s32[2 * (b * NS + t)] : s32[b * NS + t];
            sa += v;
            if (st == 4 || st == 5) sd += v;
        }
        __shared__ float psA[4][ND], psD[4][ND];
        psA[tg][d] = sa; psD[tg][d] = sd;
        __syncthreads();
        if (tid < ND) {
            float a = 0.f, dd = 0.f;
            #pragma unroll
            for (int g = 0; g < 4; g++) { a += psA[g][tid]; dd += psD[g][tid]; }
            g_partAll[b][c][tid]  = a;
            g_partDoor[b][c][tid] = dd;
        }
    }
}

// ---------------- K_default: out = emb + 0.5*colMean (non-switch rows only) -
__global__ void __launch_bounds__(256) k_default(const float* __restrict__ emb,
                                                 float* __restrict__ out) {
    size_t e4 = (size_t)blockIdx.x * 256 + threadIdx.x;
    int row = (int)(e4 >> 6);               // b*NS + s
    if (g_swf[row]) return;                  // switch rows owned by attn path
    int b  = (int)(e4 >> 16);
    int d4 = (int)(e4 & 63);
    float4 p0 = ((const float4*)g_partAll[b][0])[d4];
    float4 p1 = ((const float4*)g_partAll[b][1])[d4];
    float4 p2 = ((const float4*)g_partAll[b][2])[d4];
    float4 p3 = ((const float4*)g_partAll[b][3])[d4];
    const float kk = 0.5f / 1024.f;
    float4 v = ((const float4*)emb)[e4];
    v.x += (p0.x + p1.x + p2.x + p3.x) * kk;
    v.y += (p0.y + p1.y + p2.y + p3.y) * kk;
    v.z += (p0.z + p1.z + p2.z + p3.z) * kk;
    v.w += (p0.w + p1.w + p2.w + p3.w) * kk;
    ((float4*)out)[e4] = v;
}

// ---------------- K_z: K-split partial z, 64 rows x 128 e, 8 stages ---------
// blockIdx.z encodes (mt, ks): each block sums d in [ks*128,(ks+1)*128).
__global__ void __launch_bounds__(256) k_z(const float* __restrict__ emb) {
    int et = blockIdx.x, b = blockIdx.y;
    int mt = blockIdx.z >> 1, ks = blockIdx.z & 1;
    int nsw = g_nsw[b];
    if (mt * 64 >= nsw) return;
    int tid = threadIdx.x;
    __shared__ float Xs[2][16][68];
    __shared__ float Ms[2][16][132];
    __shared__ const float* rp[64];
    if (tid < 64) {
        int slot = mt * 64 + tid;
        rp[tid] = emb + ((size_t)b * NS + g_sw_idx[b][min(slot, nsw - 1)]) * ND;
    }
    __syncthreads();
    const int K0 = ks * 128;
    const int xrow = tid >> 2, xk4 = (tid & 3) * 4;
    const int mkr = tid >> 5,  me4 = (tid & 31) * 4;
    const int rg = tid >> 4, eg = tid & 15;
    const float* xp = rp[xrow];
    const float* mp = &g_M[0][et * 128 + me4];

    float4 xv = *(const float4*)(xp + K0 + xk4);
    float4 ma = *(const float4*)(mp + (size_t)(K0 + mkr) * ND);
    float4 mb = *(const float4*)(mp + (size_t)(K0 + mkr + 8) * ND);
    Xs[0][xk4 + 0][xrow] = xv.x; Xs[0][xk4 + 1][xrow] = xv.y;
    Xs[0][xk4 + 2][xrow] = xv.z; Xs[0][xk4 + 3][xrow] = xv.w;
    *(float4*)&Ms[0][mkr][me4]     = ma;
    *(float4*)&Ms[0][mkr + 8][me4] = mb;
    __syncthreads();

    ull acc[4][4];
    #pragma unroll
    for (int r = 0; r < 4; r++)
        #pragma unroll
        for (int p = 0; p < 4; p++) acc[r][p] = 0ULL;

    for (int s = 0; s < 8; s++) {
        int cur = s & 1;
        if (s + 1 < 8) {
            int k0 = K0 + (s + 1) * 16;
            xv = *(const float4*)(xp + k0 + xk4);
            ma = *(const float4*)(mp + (size_t)(k0 + mkr) * ND);
            mb = *(const float4*)(mp + (size_t)(k0 + mkr + 8) * ND);
        }
        #pragma unroll
        for (int k = 0; k < 16; k++) {
            float4 xf = *(const float4*)&Xs[cur][k][rg * 4];
            ulonglong2 m0 = *(const ulonglong2*)&Ms[cur][k][eg * 8];
            ulonglong2 m1 = *(const ulonglong2*)&Ms[cur][k][eg * 8 + 4];
            ull x0 = splat2(xf.x), x1 = splat2(xf.y);
            ull x2 = splat2(xf.z), x3 = splat2(xf.w);
            FMA2(acc[0][0], x0, m0.x); FMA2(acc[0][1], x0, m0.y);
            FMA2(acc[0][2], x0, m1.x); FMA2(acc[0][3], x0, m1.y);
            FMA2(acc[1][0], x1, m0.x); FMA2(acc[1][1], x1, m0.y);
            FMA2(acc[1][2], x1, m1.x); FMA2(acc[1][3], x1, m1.y);
            FMA2(acc[2][0], x2, m0.x); FMA2(acc[2][1], x2, m0.y);
            FMA2(acc[2][2], x2, m1.x); FMA2(acc[2][3], x2, m1.y);
            FMA2(acc[3][0], x3, m0.x); FMA2(acc[3][1], x3, m0.y);
            FMA2(acc[3][2], x3, m1.x); FMA2(acc[3][3], x3, m1.y);
        }
        if (s + 1 < 8) {
            int nb2 = cur ^ 1;
            Xs[nb2][xk4 + 0][xrow] = xv.x; Xs[nb2][xk4 + 1][xrow] = xv.y;
            Xs[nb2][xk4 + 2][xrow] = xv.z; Xs[nb2][xk4 + 3][xrow] = xv.w;
            *(float4*)&Ms[nb2][mkr][me4]     = ma;
            *(float4*)&Ms[nb2][mkr + 8][me4] = mb;
            __syncthreads();
        }
    }
    #pragma unroll
    for (int r = 0; r < 4; r++) {
        int slot = mt * 64 + rg * 4 + r;
        if (slot < nsw) {
            float2 a0 = u2f(acc[r][0]), a1 = u2f(acc[r][1]);
            float2 a2 = u2f(acc[r][2]), a3 = u2f(acc[r][3]);
            float4 o0 = make_float4(a0.x, a0.y, a1.x, a1.y);
            float4 o1 = make_float4(a2.x, a2.y, a3.x, a3.y);
            *(float4*)&g_pz[ks][b][slot][et * 128 + eg * 8]     = o0;
            *(float4*)&g_pz[ks][b][slot][et * 128 + eg * 8 + 4] = o1;
        }
    }
}

// ---------------- K_attn: 4-way split-KV, 256 thr, 32i x 64j ----------------
struct AttnSmem {
    float Esh[64][260];    // door-row emb tile
    float zsh[32][260];    // z rows for this i-tile
    float ssh[64][36];     // softmax weights [j][i]
    float red[32][36];     // per-jg partial max/sum [jg][i]
    float uch[64];
    int   tj[64];
    float vch[32];
    float m[32];
    float dsum[32];
    float scale[32];
};   // ~112KB -> 2 blocks/SM

__global__ void __launch_bounds__(256, 2) k_attn(const float* __restrict__ emb,
                                                 const float* __restrict__ cwp) {
    extern __shared__ char smraw[];
    AttnSmem* S = (AttnSmem*)smraw;
    const int mt = blockIdx.x, b = blockIdx.y, js = blockIdx.z;
    const int nsw = g_nsw[b];
    const int i0 = mt * 32;
    if (i0 >= nsw) return;
    const int nd = g_ndr[b];
    const int tid = threadIdx.x;
    const int ni = min(32, nsw - i0);
    const float cwv = *cwp;

    // ---- prologue: z tile (sum of K-split partials * cw), m/dsum, vc
    for (int idx = tid; idx < 32 * 64; idx += 256) {
        int i = idx >> 6, q = idx & 63;
        float4 v = make_float4(0.f, 0.f, 0.f, 0.f);
        if (i < ni) {
            float4 a = ((const float4*)&g_pz[0][b][i0 + i][0])[q];
            float4 c = ((const float4*)&g_pz[1][b][i0 + i][0])[q];
            v = make_float4(cwv * (a.x + c.x), cwv * (a.y + c.y),
                            cwv * (a.z + c.z), cwv * (a.w + c.w));
        }
        *(float4*)&S->zsh[i][q * 4] = v;
    }
    if (tid < 32) {
        S->m[tid]    = -1e30f;   // door-side max only; non-door handled in k_comb
        S->dsum[tid] = 0.f;
    }
    {   // vc: warp w (0..7) covers rows w, w+8, w+16, w+24
        int w = tid >> 5, lane = tid & 31;
        for (int r = w; r < 32; r += 8) {
            float val = -1e30f;
            if (r < ni) {
                int srow = g_sw_idx[b][i0 + r];
                const float4* er = (const float4*)&emb[((size_t)b * NS + srow) * ND];
                const float4* vr = (const float4*)g_vecA;
                float s = 0.f;
                #pragma unroll
                for (int j2 = 0; j2 < 2; j2++) {
                    float4 e4 = er[lane + 32 * j2], v4 = vr[lane + 32 * j2];
                    s += e4.x * v4.x + e4.y * v4.y + e4.z * v4.z + e4.w * v4.w;
                }
                #pragma unroll
                for (int o = 16; o; o >>= 1) s += __shfl_down_sync(0xFFFFFFFFu, s, o);
                val = cwv * (s + g_c);
            }
            if (lane == 0) S->vch[r] = val;
        }
    }

    // this split's door range (quarter)
    const int ndq = (nd + 3) >> 2;
    const int jlo = js * ndq;
    const int myn = min(nd, jlo + ndq) - jlo;   // may be <= 0

    const int ig = tid >> 5;     // 0..7  -> i = ig*4 + r
    const int jg = tid & 31;     // 0..31 -> j = jg, jg+32

    ull accv[16];
    #pragma unroll
    for (int p = 0; p < 16; p++) accv[p] = 0ULL;

    for (int jb = 0; jb < myn; jb += 64) {
        int cnt = min(64, myn - jb);
        __syncthreads();
        if (tid < 64)
            S->tj[tid] = g_dr_idx[b][jlo + ((tid < cnt) ? (jb + tid) : jb)];
        __syncthreads();
        for (int idx = tid; idx < 64 * 64; idx += 256) {
            int j = idx >> 6, q = idx & 63;
            float4 v = ((const float4*)&emb[((size_t)b * NS + S->tj[j]) * ND])[q];
            *(float4*)&S->Esh[j][q * 4] = v;
        }
        __syncthreads();
        // ---- uc_j = cw * (E_j . vecB): 4 threads per j (vecB via L1)
        {
            int j = tid >> 2, q4 = tid & 3;
            const float4* er = (const float4*)&S->Esh[j][0];
            const float4* vr = (const float4*)g_vecB;
            float s = 0.f;
            #pragma unroll
            for (int q = 0; q < 16; q++) {
                float4 e4 = er[q4 + 4 * q], v4 = vr[q4 + 4 * q];
                s += e4.x * v4.x + e4.y * v4.y + e4.z * v4.z + e4.w * v4.w;
            }
            s += __shfl_xor_sync(0xFFFFFFFFu, s, 1);
            s += __shfl_xor_sync(0xFFFFFFFFu, s, 2);
            if (q4 == 0) S->uch[j] = (j < cnt) ? cwv * s : 0.f;
        }
        __syncthreads();
        // ---- scores: thread computes 4i x 2j over full e=256
        ull sc[4][2];
        #pragma unroll
        for (int r = 0; r < 4; r++) { sc[r][0] = 0ULL; sc[r][1] = 0ULL; }
        #pragma unroll 4
        for (int e = 0; e < ND; e += 4) {
            ulonglong2 zr0 = *(const ulonglong2*)&S->zsh[ig * 4 + 0][e];
            ulonglong2 zr1 = *(const ulonglong2*)&S->zsh[ig * 4 + 1][e];
            ulonglong2 zr2 = *(const ulonglong2*)&S->zsh[ig * 4 + 2][e];
            ulonglong2 zr3 = *(const ulonglong2*)&S->zsh[ig * 4 + 3][e];
            ulonglong2 ee0 = *(const ulonglong2*)&S->Esh[jg][e];
            ulonglong2 ee1 = *(const ulonglong2*)&S->Esh[jg + 32][e];
            FMA2(sc[0][0], zr0.x, ee0.x); FMA2(sc[0][0], zr0.y, ee0.y);
            FMA2(sc[0][1], zr0.x, ee1.x); FMA2(sc[0][1], zr0.y, ee1.y);
            FMA2(sc[1][0], zr1.x, ee0.x); FMA2(sc[1][0], zr1.y, ee0.y);
            FMA2(sc[1][1], zr1.x, ee1.x); FMA2(sc[1][1], zr1.y, ee1.y);
            FMA2(sc[2][0], zr2.x, ee0.x); FMA2(sc[2][0], zr2.y, ee0.y);
            FMA2(sc[2][1], zr2.x, ee1.x); FMA2(sc[2][1], zr2.y, ee1.y);
            FMA2(sc[3][0], zr3.x, ee0.x); FMA2(sc[3][0], zr3.y, ee0.y);
            FMA2(sc[3][1], zr3.x, ee1.x); FMA2(sc[3][1], zr3.y, ee1.y);
        }
        float sv[4][2];
        #pragma unroll
        for (int r = 0; r < 4; r++) {
            float vci = S->vch[ig * 4 + r];
            float lm = -1e30f;
            #pragma unroll
            for (int c = 0; c < 2; c++) {
                int j = jg + 32 * c;
                float2 a = u2f(sc[r][c]);
                float s = (a.x + a.y) + vci + S->uch[j];
                sv[r][c] = (j < cnt) ? s : -1e30f;
                lm = fmaxf(lm, sv[r][c]);
            }
            S->red[jg][ig * 4 + r] = lm;
        }
        __syncthreads();
        if (tid < 32) {
            float mo = S->m[tid], mn = mo;
            #pragma unroll 8
            for (int g = 0; g < 32; g++) mn = fmaxf(mn, S->red[g][tid]);
            S->scale[tid] = __expf(mo - mn);
            S->m[tid] = mn;
        }
        __syncthreads();
        #pragma unroll
        for (int r = 0; r < 4; r++) {
            float mi = S->m[ig * 4 + r];
            float ls = 0.f;
            #pragma unroll
            for (int c = 0; c < 2; c++) {
                float w = __expf(sv[r][c] - mi);
                S->ssh[jg + 32 * c][ig * 4 + r] = w;
                ls += w;
            }
            S->red[jg][ig * 4 + r] = ls;
        }
        __syncthreads();
        if (tid < 32) {
            float cs = 0.f;
            #pragma unroll 8
            for (int g = 0; g < 32; g++) cs += S->red[g][tid];
            S->dsum[tid] = S->dsum[tid] * S->scale[tid] + cs;
        }
        __syncthreads();
        // ---- V accumulate: thread = d (tid), 32 i's (16 ull)
        #pragma unroll
        for (int p = 0; p < 16; p++) {
            ull sp = pack2(S->scale[2 * p], S->scale[2 * p + 1]);
            accv[p] = MUL2(accv[p], sp);
        }
        #pragma unroll 2
        for (int j = 0; j < 64; j++) {
            ull ev2 = splat2(S->Esh[j][tid]);
            ulonglong2 w0 = *(const ulonglong2*)&S->ssh[j][0];
            ulonglong2 w1 = *(const ulonglong2*)&S->ssh[j][4];
            ulonglong2 w2 = *(const ulonglong2*)&S->ssh[j][8];
            ulonglong2 w3 = *(const ulonglong2*)&S->ssh[j][12];
            ulonglong2 w4 = *(const ulonglong2*)&S->ssh[j][16];
            ulonglong2 w5 = *(const ulonglong2*)&S->ssh[j][20];
            ulonglong2 w6 = *(const ulonglong2*)&S->ssh[j][24];
            ulonglong2 w7 = *(const ulonglong2*)&S->ssh[j][28];
            FMA2(accv[0],  w0.x, ev2); FMA2(accv[1],  w0.y, ev2);
            FMA2(accv[2],  w1.x, ev2); FMA2(accv[3],  w1.y, ev2);
            FMA2(accv[4],  w2.x, ev2); FMA2(accv[5],  w2.y, ev2);
            FMA2(accv[6],  w3.x, ev2); FMA2(accv[7],  w3.y, ev2);
            FMA2(accv[8],  w4.x, ev2); FMA2(accv[9],  w4.y, ev2);
            FMA2(accv[10], w5.x, ev2); FMA2(accv[11], w5.y, ev2);
            FMA2(accv[12], w6.x, ev2); FMA2(accv[13], w6.y, ev2);
            FMA2(accv[14], w7.x, ev2); FMA2(accv[15], w7.y, ev2);
        }
    }
    __syncthreads();
    // ---- write slot-indexed partials (empty split writes zeros/-1e30)
    if (tid < 32 && tid < ni) {
        g_pm[b][js][i0 + tid] = S->m[tid];
        g_pd[b][js][i0 + tid] = S->dsum[tid];
    }
    #pragma unroll
    for (int p = 0; p < 16; p++) {
        float2 ap = u2f(accv[p]);
        if (2 * p < ni)     g_pacc[b][js][i0 + 2 * p][tid]     = ap.x;
        if (2 * p + 1 < ni) g_pacc[b][js][i0 + 2 * p + 1][tid] = ap.y;
    }
}

// ---------------- K_comb: merge 4 splits + non-door term + epilogue ---------
__global__ void __launch_bounds__(256) k_comb(const float* __restrict__ emb,
                                              float* __restrict__ out) {
    const int mt = blockIdx.x, b = blockIdx.y;
    const int nsw = g_nsw[b];
    const int i0 = mt * 32;
    if (i0 >= nsw) return;
    const int nd = g_ndr[b];
    const int ni = min(32, nsw - i0);
    const int d = threadIdx.x;

    float sndv = 0.f;
    #pragma unroll
    for (int c = 0; c < 4; c++) sndv += g_partAll[b][c][d] - g_partDoor[b][c][d];

    for (int i = 0; i < ni; i++) {
        int slot = i0 + i;
        float mv[4], dv[4];
        #pragma unroll
        for (int k = 0; k < 4; k++) { mv[k] = g_pm[b][k][slot]; dv[k] = g_pd[b][k][slot]; }
        float M = fmaxf(fmaxf(mv[0], mv[1]), fmaxf(mv[2], mv[3]));
        if (nd < NS) M = fmaxf(M, 0.f);
        float den = 0.f, num = 0.f;
        #pragma unroll
        for (int k = 0; k < 4; k++) {
            float sk = __expf(mv[k] - M);
            den += dv[k] * sk;
            num += g_pacc[b][k][slot][d] * sk;
        }
        if (nd < NS) {
            float eM = __expf(-M);
            den += (float)(NS - nd) * eM;
            num += eM * sndv;
        }
        int srow = g_sw_idx[b][slot];
        size_t o = ((size_t)b * NS + srow) * ND + d;
        out[o] = emb[o] + 0.5f * (num / den);
    }
}

// ---------------- launch: fork-join graph (all forks rejoin at the end) ------
extern "C" void kernel_launch(void* const* d_in, const int* in_sizes, int n_in,
                              void* d_out, int out_size) {
    const float* emb = (const float*)d_in[0];
    const int*   s32 = (const int*)d_in[1];   // int32 or int64, detected per block
    const float* Wq  = (const float*)d_in[2];
    const float* bq  = (const float*)d_in[3];
    const float* Wk  = (const float*)d_in[4];
    const float* bk  = (const float*)d_in[5];
    const float* cw  = (const float*)d_in[6];
    // d_in[7] = causal_bias: cancels inside softmax, unused.
    float* out = (float*)d_out;

    static bool inited = false;
    static cudaStream_t s1, s2;
    static cudaEvent_t eFork, eP, eD;
    if (!inited) {
        cudaStreamCreateWithFlags(&s1, cudaStreamNonBlocking);
        cudaStreamCreateWithFlags(&s2, cudaStreamNonBlocking);
        cudaEventCreateWithFlags(&eFork, cudaEventDisableTiming);
        cudaEventCreateWithFlags(&eP,    cudaEventDisableTiming);
        cudaEventCreateWithFlags(&eD,    cudaEventDisableTiming);
        cudaFuncSetAttribute(k_attn, cudaFuncAttributeMaxDynamicSharedMemorySize,
                             (int)sizeof(AttnSmem));
        inited = true;
    }

    cudaEventRecord(eFork, 0);
    cudaStreamWaitEvent(s1, eFork, 0);
    cudaStreamWaitEvent(s2, eFork, 0);

    // launch 1-2: k_M (main) || k_prep2 (s1)
    k_M<<<65, 256>>>(Wq, Wk, bq, bk);
    k_prep2<<<dim3(NB, 5), 1024, 0, s1>>>(s32, emb);
    cudaEventRecord(eP, s1);

    // launch 3: k_z K-split (main; needs M + masks)
    cudaStreamWaitEvent(0, eP, 0);
    k_z<<<dim3(2, NB, 32), 256>>>(emb);

    // launch 4: k_attn 4-way split-KV (main) — ncu target
    k_attn<<<dim3(NS / 32, NB, 4), 256, sizeof(AttnSmem)>>>(emb, cw);

    // launch 5: k_comb (main; merges splits, writes switch rows of out)
    k_comb<<<dim3(NS / 32, NB), 256>>>(emb, out);

    // launch 6: k_default (s2; row-disjoint with k_comb; rejoin at the end)
    cudaStreamWaitEvent(s2, eP, 0);
    k_default<<<(NB * NS * (ND / 4)) / 256, 256, 0, s2>>>(emb, out);
    cudaEventRecord(eD, s2);
    cudaStreamWaitEvent(0, eD, 0);
}

// round 16
// speedup vs baseline: 1.1396x; 1.1396x over previous
#include <cuda_runtime.h>
#include <cuda_bf16.h>

#define NB 32
#define NS 1024
#define ND 256

typedef unsigned long long ull;

// ---------------- packed f32x2 helpers --------------------------------------
__device__ __forceinline__ void FMA2(ull& d, ull a, ull b) {
    asm("fma.rn.f32x2 %0, %1, %2, %0;" : "+l"(d) : "l"(a), "l"(b));
}
__device__ __forceinline__ ull MUL2(ull a, ull b) {
    ull d;
    asm("mul.rn.f32x2 %0, %1, %2;" : "=l"(d) : "l"(a), "l"(b));
    return d;
}
__device__ __forceinline__ ull splat2(float v) {
    ull r;
    asm("mov.b64 %0, {%1, %1};" : "=l"(r) : "f"(v));
    return r;
}
__device__ __forceinline__ ull pack2(float x, float y) {
    ull r;
    asm("mov.b64 %0, {%1, %2};" : "=l"(r) : "f"(x), "f"(y));
    return r;
}
__device__ __forceinline__ float2 u2f(ull v) {
    float2 r;
    asm("mov.b64 {%0, %1}, %2;" : "=f"(r.x), "=f"(r.y) : "l"(v));
    return r;
}

// ---------------- scratch (static __device__, no allocation) ----------------
__device__ __align__(16) float g_M[ND][ND];     // M[d][e] = sum_a Wq[a][d]*Wk[a][e]
__device__ __align__(16) float g_vecA[ND];      // Wq^T bk
__device__ __align__(16) float g_vecB[ND];      // Wk^T bq
__device__ float g_c;                           // bq . bk
__device__ int   g_sw_idx[NB][NS];
__device__ int   g_dr_idx[NB][NS];
__device__ int   g_nsw[NB];
__device__ int   g_ndr[NB];
__device__ int   g_swf[NB * NS];                // 1 iff switch row
__device__ __align__(16) float g_partAll[NB][4][ND];
__device__ __align__(16) float g_partDoor[NB][4][ND];
__device__ __align__(16) float g_pz[2][NB][NS][ND];     // K-split z partials (no cw)
// split-KV partials, indexed by switch SLOT
__device__ __align__(16) float g_pm[NB][2][NS];
__device__ __align__(16) float g_pd[NB][2][NS];
__device__ __align__(16) float g_pacc[NB][2][NS][ND];

// ---------------- K_M: M = Wq^T Wk (32x32 tiles) + bias vectors + c ---------
__global__ void __launch_bounds__(256) k_M(const float* __restrict__ Wq,
                                           const float* __restrict__ Wk,
                                           const float* __restrict__ bq,
                                           const float* __restrict__ bk) {
    int tid = threadIdx.x;
    if (blockIdx.x == 64) {
        int d = tid;
        float va = 0.f, vb = 0.f;
        #pragma unroll 8
        for (int a = 0; a < ND; a++) {
            va += Wq[a * ND + d] * bk[a];
            vb += Wk[a * ND + d] * bq[a];
        }
        g_vecA[d] = va;
        g_vecB[d] = vb;
        if (tid < 32) {
            float c = 0.f;
            for (int i = tid; i < ND; i += 32) c += bq[i] * bk[i];
            #pragma unroll
            for (int o = 16; o; o >>= 1) c += __shfl_down_sync(0xFFFFFFFFu, c, o);
            if (tid == 0) g_c = c;
        }
        return;
    }
    int dt = blockIdx.x >> 3, et = blockIdx.x & 7;
    __shared__ float As[16][32], Bs[16][32];
    float a00 = 0.f, a01 = 0.f, a10 = 0.f, a11 = 0.f;
    int dg = tid >> 4, eg = tid & 15;
    int al = tid >> 4, c2 = (tid & 15) * 2;
    for (int a0 = 0; a0 < ND; a0 += 16) {
        *(float2*)&As[al][c2] = *(const float2*)&Wq[(a0 + al) * ND + dt * 32 + c2];
        *(float2*)&Bs[al][c2] = *(const float2*)&Wk[(a0 + al) * ND + et * 32 + c2];
        __syncthreads();
        #pragma unroll
        for (int k = 0; k < 16; k++) {
            float2 av = *(const float2*)&As[k][dg * 2];
            float2 bv = *(const float2*)&Bs[k][eg * 2];
            a00 += av.x * bv.x; a01 += av.x * bv.y;
            a10 += av.y * bv.x; a11 += av.y * bv.y;
        }
        __syncthreads();
    }
    int d = dt * 32 + dg * 2, e = et * 32 + eg * 2;
    g_M[d][e]     = a00; g_M[d][e + 1]     = a01;
    g_M[d + 1][e] = a10; g_M[d + 1][e + 1] = a11;
}

// ---------------- K_prep2: dtype detect + masks/flags (bz0) | colsum --------
__global__ void __launch_bounds__(1024) k_prep2(const int* __restrict__ s32,
                                                const float* __restrict__ emb) {
    int b = blockIdx.x, bz = blockIdx.y, tid = threadIdx.x;
    int vdet = (tid < 512) ? s32[b * NS + 2 * tid + 1] : 0;
    int is64 = !__syncthreads_or(vdet != 0);

    if (bz == 0) {
        int t = tid;
        int st = is64 ? s32[2 * (b * NS + t)] : s32[b * NS + t];
        int isw = (st == 3), idr = (st == 4 || st == 5);
        g_swf[b * NS + t] = isw;
        unsigned mw = __ballot_sync(0xFFFFFFFFu, isw);
        unsigned md = __ballot_sync(0xFFFFFFFFu, idr);
        int lane = t & 31, w = t >> 5;
        __shared__ int cw_[32], cd_[32], ow_[32], od_[32];
        if (lane == 0) { cw_[w] = __popc(mw); cd_[w] = __popc(md); }
        __syncthreads();
        if (tid == 0) {
            int aw = 0, ad = 0;
            for (int i = 0; i < 32; i++) {
                ow_[i] = aw; aw += cw_[i];
                od_[i] = ad; ad += cd_[i];
            }
            g_nsw[b] = aw; g_ndr[b] = ad;
        }
        __syncthreads();
        if (isw) g_sw_idx[b][ow_[w] + __popc(mw & ((1u << lane) - 1u))] = t;
        if (idr) g_dr_idx[b][od_[w] + __popc(md & ((1u << lane) - 1u))] = t;
    } else {
        int c = bz - 1, tg = tid >> 8, d = tid & 255;
        float sa = 0.f, sd = 0.f;
        int tb = c * 256 + tg * 64;
        #pragma unroll 4
        for (int i = 0; i < 64; i++) {
            int t = tb + i;
            float v = emb[((size_t)b * NS + t) * ND + d];
            int st = is64 ? s32[2 * (b * NS + t)] : s32[b * NS + t];
            sa += v;
            if (st == 4 || st == 5) sd += v;
        }
        __shared__ float psA[4][ND], psD[4][ND];
        psA[tg][d] = sa; psD[tg][d] = sd;
        __syncthreads();
        if (tid < ND) {
            float a = 0.f, dd = 0.f;
            #pragma unroll
            for (int g = 0; g < 4; g++) { a += psA[g][tid]; dd += psD[g][tid]; }
            g_partAll[b][c][tid]  = a;
            g_partDoor[b][c][tid] = dd;
        }
    }
}

// ---------------- K_default: out = emb + 0.5*colMean (non-switch rows only) -
__global__ void __launch_bounds__(256) k_default(const float* __restrict__ emb,
                                                 float* __restrict__ out) {
    size_t e4 = (size_t)blockIdx.x * 256 + threadIdx.x;
    int row = (int)(e4 >> 6);               // b*NS + s
    if (g_swf[row]) return;                  // switch rows owned by attn path
    int b  = (int)(e4 >> 16);
    int d4 = (int)(e4 & 63);
    float4 p0 = ((const float4*)g_partAll[b][0])[d4];
    float4 p1 = ((const float4*)g_partAll[b][1])[d4];
    float4 p2 = ((const float4*)g_partAll[b][2])[d4];
    float4 p3 = ((const float4*)g_partAll[b][3])[d4];
    const float kk = 0.5f / 1024.f;
    float4 v = ((const float4*)emb)[e4];
    v.x += (p0.x + p1.x + p2.x + p3.x) * kk;
    v.y += (p0.y + p1.y + p2.y + p3.y) * kk;
    v.z += (p0.z + p1.z + p2.z + p3.z) * kk;
    v.w += (p0.w + p1.w + p2.w + p3.w) * kk;
    ((float4*)out)[e4] = v;
}

// ---------------- K_z: K-split partial z, 64 rows x 128 e, 8 stages ---------
// blockIdx.z encodes (mt, ks): each block sums d in [ks*128,(ks+1)*128).
// Same total M traffic as the 16-stage version, 2x live blocks.
__global__ void __launch_bounds__(256) k_z(const float* __restrict__ emb) {
    int et = blockIdx.x, b = blockIdx.y;
    int mt = blockIdx.z >> 1, ks = blockIdx.z & 1;
    int nsw = g_nsw[b];
    if (mt * 64 >= nsw) return;
    int tid = threadIdx.x;
    __shared__ float Xs[2][16][68];
    __shared__ float Ms[2][16][132];
    __shared__ const float* rp[64];
    if (tid < 64) {
        int slot = mt * 64 + tid;
        rp[tid] = emb + ((size_t)b * NS + g_sw_idx[b][min(slot, nsw - 1)]) * ND;
    }
    __syncthreads();
    const int K0 = ks * 128;
    const int xrow = tid >> 2, xk4 = (tid & 3) * 4;
    const int mkr = tid >> 5,  me4 = (tid & 31) * 4;
    const int rg = tid >> 4, eg = tid & 15;
    const float* xp = rp[xrow];
    const float* mp = &g_M[0][et * 128 + me4];

    float4 xv = *(const float4*)(xp + K0 + xk4);
    float4 ma = *(const float4*)(mp + (size_t)(K0 + mkr) * ND);
    float4 mb = *(const float4*)(mp + (size_t)(K0 + mkr + 8) * ND);
    Xs[0][xk4 + 0][xrow] = xv.x; Xs[0][xk4 + 1][xrow] = xv.y;
    Xs[0][xk4 + 2][xrow] = xv.z; Xs[0][xk4 + 3][xrow] = xv.w;
    *(float4*)&Ms[0][mkr][me4]     = ma;
    *(float4*)&Ms[0][mkr + 8][me4] = mb;
    __syncthreads();

    ull acc[4][4];
    #pragma unroll
    for (int r = 0; r < 4; r++)
        #pragma unroll
        for (int p = 0; p < 4; p++) acc[r][p] = 0ULL;

    for (int s = 0; s < 8; s++) {
        int cur = s & 1;
        if (s + 1 < 8) {
            int k0 = K0 + (s + 1) * 16;
            xv = *(const float4*)(xp + k0 + xk4);
            ma = *(const float4*)(mp + (size_t)(k0 + mkr) * ND);
            mb = *(const float4*)(mp + (size_t)(k0 + mkr + 8) * ND);
        }
        #pragma unroll
        for (int k = 0; k < 16; k++) {
            float4 xf = *(const float4*)&Xs[cur][k][rg * 4];
            ulonglong2 m0 = *(const ulonglong2*)&Ms[cur][k][eg * 8];
            ulonglong2 m1 = *(const ulonglong2*)&Ms[cur][k][eg * 8 + 4];
            ull x0 = splat2(xf.x), x1 = splat2(xf.y);
            ull x2 = splat2(xf.z), x3 = splat2(xf.w);
            FMA2(acc[0][0], x0, m0.x); FMA2(acc[0][1], x0, m0.y);
            FMA2(acc[0][2], x0, m1.x); FMA2(acc[0][3], x0, m1.y);
            FMA2(acc[1][0], x1, m0.x); FMA2(acc[1][1], x1, m0.y);
            FMA2(acc[1][2], x1, m1.x); FMA2(acc[1][3], x1, m1.y);
            FMA2(acc[2][0], x2, m0.x); FMA2(acc[2][1], x2, m0.y);
            FMA2(acc[2][2], x2, m1.x); FMA2(acc[2][3], x2, m1.y);
            FMA2(acc[3][0], x3, m0.x); FMA2(acc[3][1], x3, m0.y);
            FMA2(acc[3][2], x3, m1.x); FMA2(acc[3][3], x3, m1.y);
        }
        if (s + 1 < 8) {
            int nb2 = cur ^ 1;
            Xs[nb2][xk4 + 0][xrow] = xv.x; Xs[nb2][xk4 + 1][xrow] = xv.y;
            Xs[nb2][xk4 + 2][xrow] = xv.z; Xs[nb2][xk4 + 3][xrow] = xv.w;
            *(float4*)&Ms[nb2][mkr][me4]     = ma;
            *(float4*)&Ms[nb2][mkr + 8][me4] = mb;
            __syncthreads();
        }
    }
    #pragma unroll
    for (int r = 0; r < 4; r++) {
        int slot = mt * 64 + rg * 4 + r;
        if (slot < nsw) {
            float2 a0 = u2f(acc[r][0]), a1 = u2f(acc[r][1]);
            float2 a2 = u2f(acc[r][2]), a3 = u2f(acc[r][3]);
            float4 o0 = make_float4(a0.x, a0.y, a1.x, a1.y);
            float4 o1 = make_float4(a2.x, a2.y, a3.x, a3.y);
            *(float4*)&g_pz[ks][b][slot][et * 128 + eg * 8]     = o0;
            *(float4*)&g_pz[ks][b][slot][et * 128 + eg * 8 + 4] = o1;
        }
    }
}

// ---------------- K_attn: 2-way split-KV, 256 thr, 32i x 64j ----------------
struct AttnSmem {
    float Esh[64][260];    // door-row emb tile
    float zsh[32][260];    // z rows for this i-tile
    float ssh[64][36];     // softmax weights [j][i]
    float red[32][36];     // per-jg partial max/sum [jg][i]
    float uch[64];
    int   tj[64];
    float vch[32];
    float m[32];
    float dsum[32];
    float scale[32];
};   // ~112KB -> 2 blocks/SM

__global__ void __launch_bounds__(256, 2) k_attn(const float* __restrict__ emb,
                                                 const float* __restrict__ cwp) {
    extern __shared__ char smraw[];
    AttnSmem* S = (AttnSmem*)smraw;
    const int mt = blockIdx.x, b = blockIdx.y, js = blockIdx.z;
    const int nsw = g_nsw[b];
    const int i0 = mt * 32;
    if (i0 >= nsw) return;
    const int nd = g_ndr[b];
    const int tid = threadIdx.x;
    const int ni = min(32, nsw - i0);
    const float cwv = *cwp;

    // ---- prologue: z tile (sum of K-split partials * cw), m/dsum, vc
    for (int idx = tid; idx < 32 * 64; idx += 256) {
        int i = idx >> 6, q = idx & 63;
        float4 v = make_float4(0.f, 0.f, 0.f, 0.f);
        if (i < ni) {
            float4 a = ((const float4*)&g_pz[0][b][i0 + i][0])[q];
            float4 c = ((const float4*)&g_pz[1][b][i0 + i][0])[q];
            v = make_float4(cwv * (a.x + c.x), cwv * (a.y + c.y),
                            cwv * (a.z + c.z), cwv * (a.w + c.w));
        }
        *(float4*)&S->zsh[i][q * 4] = v;
    }
    if (tid < 32) {
        S->m[tid]    = -1e30f;   // door-side max only; non-door handled in k_comb
        S->dsum[tid] = 0.f;
    }
    {   // vc: warp w (0..7) covers rows w, w+8, w+16, w+24
        int w = tid >> 5, lane = tid & 31;
        for (int r = w; r < 32; r += 8) {
            float val = -1e30f;
            if (r < ni) {
                int srow = g_sw_idx[b][i0 + r];
                const float4* er = (const float4*)&emb[((size_t)b * NS + srow) * ND];
                const float4* vr = (const float4*)g_vecA;
                float s = 0.f;
                #pragma unroll
                for (int j2 = 0; j2 < 2; j2++) {
                    float4 e4 = er[lane + 32 * j2], v4 = vr[lane + 32 * j2];
                    s += e4.x * v4.x + e4.y * v4.y + e4.z * v4.z + e4.w * v4.w;
                }
                #pragma unroll
                for (int o = 16; o; o >>= 1) s += __shfl_down_sync(0xFFFFFFFFu, s, o);
                val = cwv * (s + g_c);
            }
            if (lane == 0) S->vch[r] = val;
        }
    }

    // this split's door range (half)
    const int ndh = (nd + 1) >> 1;
    const int jlo = js * ndh;
    const int myn = min(nd, jlo + ndh) - jlo;   // may be <= 0

    const int ig = tid >> 5;     // 0..7  -> i = ig*4 + r
    const int jg = tid & 31;     // 0..31 -> j = jg, jg+32

    ull accv[16];
    #pragma unroll
    for (int p = 0; p < 16; p++) accv[p] = 0ULL;

    for (int jb = 0; jb < myn; jb += 64) {
        int cnt = min(64, myn - jb);
        __syncthreads();
        if (tid < 64)
            S->tj[tid] = g_dr_idx[b][jlo + ((tid < cnt) ? (jb + tid) : jb)];
        __syncthreads();
        for (int idx = tid; idx < 64 * 64; idx += 256) {
            int j = idx >> 6, q = idx & 63;
            float4 v = ((const float4*)&emb[((size_t)b * NS + S->tj[j]) * ND])[q];
            *(float4*)&S->Esh[j][q * 4] = v;
        }
        __syncthreads();
        // ---- uc_j = cw * (E_j . vecB): 4 threads per j (vecB via L1)
        {
            int j = tid >> 2, q4 = tid & 3;
            const float4* er = (const float4*)&S->Esh[j][0];
            const float4* vr = (const float4*)g_vecB;
            float s = 0.f;
            #pragma unroll
            for (int q = 0; q < 16; q++) {
                float4 e4 = er[q4 + 4 * q], v4 = vr[q4 + 4 * q];
                s += e4.x * v4.x + e4.y * v4.y + e4.z * v4.z + e4.w * v4.w;
            }
            s += __shfl_xor_sync(0xFFFFFFFFu, s, 1);
            s += __shfl_xor_sync(0xFFFFFFFFu, s, 2);
            if (q4 == 0) S->uch[j] = (j < cnt) ? cwv * s : 0.f;
        }
        __syncthreads();
        // ---- scores: thread computes 4i x 2j over full e=256
        ull sc[4][2];
        #pragma unroll
        for (int r = 0; r < 4; r++) { sc[r][0] = 0ULL; sc[r][1] = 0ULL; }
        #pragma unroll 4
        for (int e = 0; e < ND; e += 4) {
            ulonglong2 zr0 = *(const ulonglong2*)&S->zsh[ig * 4 + 0][e];
            ulonglong2 zr1 = *(const ulonglong2*)&S->zsh[ig * 4 + 1][e];
            ulonglong2 zr2 = *(const ulonglong2*)&S->zsh[ig * 4 + 2][e];
            ulonglong2 zr3 = *(const ulonglong2*)&S->zsh[ig * 4 + 3][e];
            ulonglong2 ee0 = *(const ulonglong2*)&S->Esh[jg][e];
            ulonglong2 ee1 = *(const ulonglong2*)&S->Esh[jg + 32][e];
            FMA2(sc[0][0], zr0.x, ee0.x); FMA2(sc[0][0], zr0.y, ee0.y);
            FMA2(sc[0][1], zr0.x, ee1.x); FMA2(sc[0][1], zr0.y, ee1.y);
            FMA2(sc[1][0], zr1.x, ee0.x); FMA2(sc[1][0], zr1.y, ee0.y);
            FMA2(sc[1][1], zr1.x, ee1.x); FMA2(sc[1][1], zr1.y, ee1.y);
            FMA2(sc[2][0], zr2.x, ee0.x); FMA2(sc[2][0], zr2.y, ee0.y);
            FMA2(sc[2][1], zr2.x, ee1.x); FMA2(sc[2][1], zr2.y, ee1.y);
            FMA2(sc[3][0], zr3.x, ee0.x); FMA2(sc[3][0], zr3.y, ee0.y);
            FMA2(sc[3][1], zr3.x, ee1.x); FMA2(sc[3][1], zr3.y, ee1.y);
        }
        float sv[4][2];
        #pragma unroll
        for (int r = 0; r < 4; r++) {
            float vci = S->vch[ig * 4 + r];
            float lm = -1e30f;
            #pragma unroll
            for (int c = 0; c < 2; c++) {
                int j = jg + 32 * c;
                float2 a = u2f(sc[r][c]);
                float s = (a.x + a.y) + vci + S->uch[j];
                sv[r][c] = (j < cnt) ? s : -1e30f;
                lm = fmaxf(lm, sv[r][c]);
            }
            S->red[jg][ig * 4 + r] = lm;
        }
        __syncthreads();
        if (tid < 32) {
            float mo = S->m[tid], mn = mo;
            #pragma unroll 8
            for (int g = 0; g < 32; g++) mn = fmaxf(mn, S->red[g][tid]);
            S->scale[tid] = __expf(mo - mn);
            S->m[tid] = mn;
        }
        __syncthreads();
        #pragma unroll
        for (int r = 0; r < 4; r++) {
            float mi = S->m[ig * 4 + r];
            float ls = 0.f;
            #pragma unroll
            for (int c = 0; c < 2; c++) {
                float w = __expf(sv[r][c] - mi);
                S->ssh[jg + 32 * c][ig * 4 + r] = w;
                ls += w;
            }
            S->red[jg][ig * 4 + r] = ls;
        }
        __syncthreads();
        if (tid < 32) {
            float cs = 0.f;
            #pragma unroll 8
            for (int g = 0; g < 32; g++) cs += S->red[g][tid];
            S->dsum[tid] = S->dsum[tid] * S->scale[tid] + cs;
        }
        __syncthreads();
        // ---- V accumulate: thread = d (tid), 32 i's (16 ull)
        #pragma unroll
        for (int p = 0; p < 16; p++) {
            ull sp = pack2(S->scale[2 * p], S->scale[2 * p + 1]);
            accv[p] = MUL2(accv[p], sp);
        }
        #pragma unroll 2
        for (int j = 0; j < 64; j++) {
            ull ev2 = splat2(S->Esh[j][tid]);
            ulonglong2 w0 = *(const ulonglong2*)&S->ssh[j][0];
            ulonglong2 w1 = *(const ulonglong2*)&S->ssh[j][4];
            ulonglong2 w2 = *(const ulonglong2*)&S->ssh[j][8];
            ulonglong2 w3 = *(const ulonglong2*)&S->ssh[j][12];
            ulonglong2 w4 = *(const ulonglong2*)&S->ssh[j][16];
            ulonglong2 w5 = *(const ulonglong2*)&S->ssh[j][20];
            ulonglong2 w6 = *(const ulonglong2*)&S->ssh[j][24];
            ulonglong2 w7 = *(const ulonglong2*)&S->ssh[j][28];
            FMA2(accv[0],  w0.x, ev2); FMA2(accv[1],  w0.y, ev2);
            FMA2(accv[2],  w1.x, ev2); FMA2(accv[3],  w1.y, ev2);
            FMA2(accv[4],  w2.x, ev2); FMA2(accv[5],  w2.y, ev2);
            FMA2(accv[6],  w3.x, ev2); FMA2(accv[7],  w3.y, ev2);
            FMA2(accv[8],  w4.x, ev2); FMA2(accv[9],  w4.y, ev2);
            FMA2(accv[10], w5.x, ev2); FMA2(accv[11], w5.y, ev2);
            FMA2(accv[12], w6.x, ev2); FMA2(accv[13], w6.y, ev2);
            FMA2(accv[14], w7.x, ev2); FMA2(accv[15], w7.y, ev2);
        }
    }
    __syncthreads();
    // ---- write slot-indexed partials (empty split writes zeros/-1e30)
    if (tid < 32 && tid < ni) {
        g_pm[b][js][i0 + tid] = S->m[tid];
        g_pd[b][js][i0 + tid] = S->dsum[tid];
    }
    #pragma unroll
    for (int p = 0; p < 16; p++) {
        float2 ap = u2f(accv[p]);
        if (2 * p < ni)     g_pacc[b][js][i0 + 2 * p][tid]     = ap.x;
        if (2 * p + 1 < ni) g_pacc[b][js][i0 + 2 * p + 1][tid] = ap.y;
    }
}

// ---------------- K_comb: merge 2 splits + non-door term + epilogue ---------
__global__ void __launch_bounds__(256) k_comb(const float* __restrict__ emb,
                                              float* __restrict__ out) {
    const int mt = blockIdx.x, b = blockIdx.y;
    const int nsw = g_nsw[b];
    const int i0 = mt * 32;
    if (i0 >= nsw) return;
    const int nd = g_ndr[b];
    const int ni = min(32, nsw - i0);
    const int d = threadIdx.x;

    float sndv = 0.f;
    #pragma unroll
    for (int c = 0; c < 4; c++) sndv += g_partAll[b][c][d] - g_partDoor[b][c][d];

    for (int i = 0; i < ni; i++) {
        int slot = i0 + i;
        float m0 = g_pm[b][0][slot], m1 = g_pm[b][1][slot];
        float d0 = g_pd[b][0][slot], d1 = g_pd[b][1][slot];
        float M = fmaxf(m0, m1);
        if (nd < NS) M = fmaxf(M, 0.f);
        float s0 = __expf(m0 - M), s1 = __expf(m1 - M);
        float a0 = g_pacc[b][0][slot][d], a1 = g_pacc[b][1][slot][d];
        float den = d0 * s0 + d1 * s1;
        float num = a0 * s0 + a1 * s1;
        if (nd < NS) {
            float eM = __expf(-M);
            den += (float)(NS - nd) * eM;
            num += eM * sndv;
        }
        int srow = g_sw_idx[b][slot];
        size_t o = ((size_t)b * NS + srow) * ND + d;
        out[o] = emb[o] + 0.5f * (num / den);
    }
}

// ---------------- launch: fork-join graph (all forks rejoin at the end) ------
extern "C" void kernel_launch(void* const* d_in, const int* in_sizes, int n_in,
                              void* d_out, int out_size) {
    const float* emb = (const float*)d_in[0];
    const int*   s32 = (const int*)d_in[1];   // int32 or int64, detected per block
    const float* Wq  = (const float*)d_in[2];
    const float* bq  = (const float*)d_in[3];
    const float* Wk  = (const float*)d_in[4];
    const float* bk  = (const float*)d_in[5];
    const float* cw  = (const float*)d_in[6];
    // d_in[7] = causal_bias: cancels inside softmax, unused.
    float* out = (float*)d_out;

    static bool inited = false;
    static cudaStream_t s1, s2;
    static cudaEvent_t eFork, eP, eD;
    if (!inited) {
        cudaStreamCreateWithFlags(&s1, cudaStreamNonBlocking);
        cudaStreamCreateWithFlags(&s2, cudaStreamNonBlocking);
        cudaEventCreateWithFlags(&eFork, cudaEventDisableTiming);
        cudaEventCreateWithFlags(&eP,    cudaEventDisableTiming);
        cudaEventCreateWithFlags(&eD,    cudaEventDisableTiming);
        cudaFuncSetAttribute(k_attn, cudaFuncAttributeMaxDynamicSharedMemorySize,
                             (int)sizeof(AttnSmem));
        inited = true;
    }

    cudaEventRecord(eFork, 0);
    cudaStreamWaitEvent(s1, eFork, 0);
    cudaStreamWaitEvent(s2, eFork, 0);

    // launch 1-2: k_M (main) || k_prep2 (s1)
    k_M<<<65, 256>>>(Wq, Wk, bq, bk);
    k_prep2<<<dim3(NB, 5), 1024, 0, s1>>>(s32, emb);
    cudaEventRecord(eP, s1);

    // launch 3: k_z K-split (main; needs M + masks) — 2x blocks, same traffic
    cudaStreamWaitEvent(0, eP, 0);
    k_z<<<dim3(2, NB, 32), 256>>>(emb);

    // launch 4: k_attn 2-way split-KV (main) — ncu target
    k_attn<<<dim3(NS / 32, NB, 2), 256, sizeof(AttnSmem)>>>(emb, cw);

    // launch 5: k_comb (main; merges splits, writes switch rows of out)
    k_comb<<<dim3(NS / 32, NB), 256>>>(emb, out);

    // launch 6: k_default (s2; row-disjoint with k_comb; rejoin at the end)
    cudaStreamWaitEvent(s2, eP, 0);
    k_default<<<(NB * NS * (ND / 4)) / 256, 256, 0, s2>>>(emb, out);
    cudaEventRecord(eD, s2);
    cudaStreamWaitEvent(0, eD, 0);
}

// round 17
// speedup vs baseline: 1.1737x; 1.0299x over previous
#include <cuda_runtime.h>
#include <cuda_bf16.h>

#define NB 32
#define NS 1024
#define ND 256

typedef unsigned long long ull;

// ---------------- packed f32x2 helpers --------------------------------------
__device__ __forceinline__ void FMA2(ull& d, ull a, ull b) {
    asm("fma.rn.f32x2 %0, %1, %2, %0;" : "+l"(d) : "l"(a), "l"(b));
}
__device__ __forceinline__ ull MUL2(ull a, ull b) {
    ull d;
    asm("mul.rn.f32x2 %0, %1, %2;" : "=l"(d) : "l"(a), "l"(b));
    return d;
}
__device__ __forceinline__ ull splat2(float v) {
    ull r;
    asm("mov.b64 %0, {%1, %1};" : "=l"(r) : "f"(v));
    return r;
}
__device__ __forceinline__ ull pack2(float x, float y) {
    ull r;
    asm("mov.b64 %0, {%1, %2};" : "=l"(r) : "f"(x), "f"(y));
    return r;
}
__device__ __forceinline__ float2 u2f(ull v) {
    float2 r;
    asm("mov.b64 {%0, %1}, %2;" : "=f"(r.x), "=f"(r.y) : "l"(v));
    return r;
}

// ---------------- scratch (static __device__, no allocation) ----------------
__device__ __align__(16) float g_M[ND][ND];     // M[d][e] = sum_a Wq[a][d]*Wk[a][e]
__device__ __align__(16) float g_vecA[ND];      // Wq^T bk
__device__ __align__(16) float g_vecB[ND];      // Wk^T bq
__device__ float g_c;                           // bq . bk
__device__ int   g_sw_idx[NB][NS];
__device__ int   g_dr_idx[NB][NS];
__device__ int   g_nsw[NB];
__device__ int   g_ndr[NB];
__device__ int   g_swf[NB * NS];                // 1 iff switch row
__device__ __align__(16) float g_partAll[NB][4][ND];
__device__ __align__(16) float g_partDoor[NB][4][ND];
__device__ __align__(16) float g_pz[2][NB][NS][ND];     // K-split z partials (no cw)
// split-KV partials, indexed by switch SLOT
__device__ __align__(16) float g_pm[NB][2][NS];
__device__ __align__(16) float g_pd[NB][2][NS];
__device__ __align__(16) float g_pacc[NB][2][NS][ND];
__device__ int g_cnt[NB][32];                    // last-block merge counters (0-init)

// ---------------- K_M: M = Wq^T Wk (32x32 tiles) + bias vectors + c ---------
__global__ void __launch_bounds__(256) k_M(const float* __restrict__ Wq,
                                           const float* __restrict__ Wk,
                                           const float* __restrict__ bq,
                                           const float* __restrict__ bk) {
    int tid = threadIdx.x;
    if (blockIdx.x == 64) {
        int d = tid;
        float va = 0.f, vb = 0.f;
        #pragma unroll 8
        for (int a = 0; a < ND; a++) {
            va += Wq[a * ND + d] * bk[a];
            vb += Wk[a * ND + d] * bq[a];
        }
        g_vecA[d] = va;
        g_vecB[d] = vb;
        if (tid < 32) {
            float c = 0.f;
            for (int i = tid; i < ND; i += 32) c += bq[i] * bk[i];
            #pragma unroll
            for (int o = 16; o; o >>= 1) c += __shfl_down_sync(0xFFFFFFFFu, c, o);
            if (tid == 0) g_c = c;
        }
        return;
    }
    int dt = blockIdx.x >> 3, et = blockIdx.x & 7;
    __shared__ float As[16][32], Bs[16][32];
    float a00 = 0.f, a01 = 0.f, a10 = 0.f, a11 = 0.f;
    int dg = tid >> 4, eg = tid & 15;
    int al = tid >> 4, c2 = (tid & 15) * 2;
    for (int a0 = 0; a0 < ND; a0 += 16) {
        *(float2*)&As[al][c2] = *(const float2*)&Wq[(a0 + al) * ND + dt * 32 + c2];
        *(float2*)&Bs[al][c2] = *(const float2*)&Wk[(a0 + al) * ND + et * 32 + c2];
        __syncthreads();
        #pragma unroll
        for (int k = 0; k < 16; k++) {
            float2 av = *(const float2*)&As[k][dg * 2];
            float2 bv = *(const float2*)&Bs[k][eg * 2];
            a00 += av.x * bv.x; a01 += av.x * bv.y;
            a10 += av.y * bv.x; a11 += av.y * bv.y;
        }
        __syncthreads();
    }
    int d = dt * 32 + dg * 2, e = et * 32 + eg * 2;
    g_M[d][e]     = a00; g_M[d][e + 1]     = a01;
    g_M[d + 1][e] = a10; g_M[d + 1][e + 1] = a11;
}

// ---------------- K_masks: dtype detect + switch/door index lists -----------
__global__ void __launch_bounds__(1024) k_masks(const int* __restrict__ s32) {
    int b = blockIdx.x, tid = threadIdx.x;
    int vdet = (tid < 512) ? s32[b * NS + 2 * tid + 1] : 0;
    int is64 = !__syncthreads_or(vdet != 0);

    int t = tid;
    int st = is64 ? s32[2 * (b * NS + t)] : s32[b * NS + t];
    int isw = (st == 3), idr = (st == 4 || st == 5);
    g_swf[b * NS + t] = isw;
    unsigned mw = __ballot_sync(0xFFFFFFFFu, isw);
    unsigned md = __ballot_sync(0xFFFFFFFFu, idr);
    int lane = t & 31, w = t >> 5;
    __shared__ int cw_[32], cd_[32], ow_[32], od_[32];
    if (lane == 0) { cw_[w] = __popc(mw); cd_[w] = __popc(md); }
    __syncthreads();
    if (tid == 0) {
        int aw = 0, ad = 0;
        for (int i = 0; i < 32; i++) {
            ow_[i] = aw; aw += cw_[i];
            od_[i] = ad; ad += cd_[i];
        }
        g_nsw[b] = aw; g_ndr[b] = ad;
    }
    __syncthreads();
    if (isw) g_sw_idx[b][ow_[w] + __popc(mw & ((1u << lane) - 1u))] = t;
    if (idr) g_dr_idx[b][od_[w] + __popc(md & ((1u << lane) - 1u))] = t;
}

// ---------------- K_colsum: partial column sums (all/door) ------------------
__global__ void __launch_bounds__(1024) k_colsum(const int* __restrict__ s32,
                                                 const float* __restrict__ emb) {
    int b = blockIdx.x, c = blockIdx.y, tid = threadIdx.x;
    int vdet = (tid < 512) ? s32[b * NS + 2 * tid + 1] : 0;
    int is64 = !__syncthreads_or(vdet != 0);

    int tg = tid >> 8, d = tid & 255;
    float sa = 0.f, sd = 0.f;
    int tb = c * 256 + tg * 64;
    #pragma unroll 4
    for (int i = 0; i < 64; i++) {
        int t = tb + i;
        float v = emb[((size_t)b * NS + t) * ND + d];
        int st = is64 ? s32[2 * (b * NS + t)] : s32[b * NS + t];
        sa += v;
        if (st == 4 || st == 5) sd += v;
    }
    __shared__ float psA[4][ND], psD[4][ND];
    psA[tg][d] = sa; psD[tg][d] = sd;
    __syncthreads();
    if (tid < ND) {
        float a = 0.f, dd = 0.f;
        #pragma unroll
        for (int g = 0; g < 4; g++) { a += psA[g][tid]; dd += psD[g][tid]; }
        g_partAll[b][c][tid]  = a;
        g_partDoor[b][c][tid] = dd;
    }
}

// ---------------- K_default: out = emb + 0.5*colMean (non-switch rows only) -
__global__ void __launch_bounds__(256) k_default(const float* __restrict__ emb,
                                                 float* __restrict__ out) {
    size_t e4 = (size_t)blockIdx.x * 256 + threadIdx.x;
    int row = (int)(e4 >> 6);               // b*NS + s
    if (g_swf[row]) return;                  // switch rows owned by attn path
    int b  = (int)(e4 >> 16);
    int d4 = (int)(e4 & 63);
    float4 p0 = ((const float4*)g_partAll[b][0])[d4];
    float4 p1 = ((const float4*)g_partAll[b][1])[d4];
    float4 p2 = ((const float4*)g_partAll[b][2])[d4];
    float4 p3 = ((const float4*)g_partAll[b][3])[d4];
    const float kk = 0.5f / 1024.f;
    float4 v = ((const float4*)emb)[e4];
    v.x += (p0.x + p1.x + p2.x + p3.x) * kk;
    v.y += (p0.y + p1.y + p2.y + p3.y) * kk;
    v.z += (p0.z + p1.z + p2.z + p3.z) * kk;
    v.w += (p0.w + p1.w + p2.w + p3.w) * kk;
    ((float4*)out)[e4] = v;
}

// ---------------- K_z: K-split partial z, 64 rows x 128 e, 8 stages ---------
__global__ void __launch_bounds__(256) k_z(const float* __restrict__ emb) {
    int et = blockIdx.x, b = blockIdx.y;
    int mt = blockIdx.z >> 1, ks = blockIdx.z & 1;
    int nsw = g_nsw[b];
    if (mt * 64 >= nsw) return;
    int tid = threadIdx.x;
    __shared__ float Xs[2][16][68];
    __shared__ float Ms[2][16][132];
    __shared__ const float* rp[64];
    if (tid < 64) {
        int slot = mt * 64 + tid;
        rp[tid] = emb + ((size_t)b * NS + g_sw_idx[b][min(slot, nsw - 1)]) * ND;
    }
    __syncthreads();
    const int K0 = ks * 128;
    const int xrow = tid >> 2, xk4 = (tid & 3) * 4;
    const int mkr = tid >> 5,  me4 = (tid & 31) * 4;
    const int rg = tid >> 4, eg = tid & 15;
    const float* xp = rp[xrow];
    const float* mp = &g_M[0][et * 128 + me4];

    float4 xv = *(const float4*)(xp + K0 + xk4);
    float4 ma = *(const float4*)(mp + (size_t)(K0 + mkr) * ND);
    float4 mb = *(const float4*)(mp + (size_t)(K0 + mkr + 8) * ND);
    Xs[0][xk4 + 0][xrow] = xv.x; Xs[0][xk4 + 1][xrow] = xv.y;
    Xs[0][xk4 + 2][xrow] = xv.z; Xs[0][xk4 + 3][xrow] = xv.w;
    *(float4*)&Ms[0][mkr][me4]     = ma;
    *(float4*)&Ms[0][mkr + 8][me4] = mb;
    __syncthreads();

    ull acc[4][4];
    #pragma unroll
    for (int r = 0; r < 4; r++)
        #pragma unroll
        for (int p = 0; p < 4; p++) acc[r][p] = 0ULL;

    for (int s = 0; s < 8; s++) {
        int cur = s & 1;
        if (s + 1 < 8) {
            int k0 = K0 + (s + 1) * 16;
            xv = *(const float4*)(xp + k0 + xk4);
            ma = *(const float4*)(mp + (size_t)(k0 + mkr) * ND);
            mb = *(const float4*)(mp + (size_t)(k0 + mkr + 8) * ND);
        }
        #pragma unroll
        for (int k = 0; k < 16; k++) {
            float4 xf = *(const float4*)&Xs[cur][k][rg * 4];
            ulonglong2 m0 = *(const ulonglong2*)&Ms[cur][k][eg * 8];
            ulonglong2 m1 = *(const ulonglong2*)&Ms[cur][k][eg * 8 + 4];
            ull x0 = splat2(xf.x), x1 = splat2(xf.y);
            ull x2 = splat2(xf.z), x3 = splat2(xf.w);
            FMA2(acc[0][0], x0, m0.x); FMA2(acc[0][1], x0, m0.y);
            FMA2(acc[0][2], x0, m1.x); FMA2(acc[0][3], x0, m1.y);
            FMA2(acc[1][0], x1, m0.x); FMA2(acc[1][1], x1, m0.y);
            FMA2(acc[1][2], x1, m1.x); FMA2(acc[1][3], x1, m1.y);
            FMA2(acc[2][0], x2, m0.x); FMA2(acc[2][1], x2, m0.y);
            FMA2(acc[2][2], x2, m1.x); FMA2(acc[2][3], x2, m1.y);
            FMA2(acc[3][0], x3, m0.x); FMA2(acc[3][1], x3, m0.y);
            FMA2(acc[3][2], x3, m1.x); FMA2(acc[3][3], x3, m1.y);
        }
        if (s + 1 < 8) {
            int nb2 = cur ^ 1;
            Xs[nb2][xk4 + 0][xrow] = xv.x; Xs[nb2][xk4 + 1][xrow] = xv.y;
            Xs[nb2][xk4 + 2][xrow] = xv.z; Xs[nb2][xk4 + 3][xrow] = xv.w;
            *(float4*)&Ms[nb2][mkr][me4]     = ma;
            *(float4*)&Ms[nb2][mkr + 8][me4] = mb;
            __syncthreads();
        }
    }
    #pragma unroll
    for (int r = 0; r < 4; r++) {
        int slot = mt * 64 + rg * 4 + r;
        if (slot < nsw) {
            float2 a0 = u2f(acc[r][0]), a1 = u2f(acc[r][1]);
            float2 a2 = u2f(acc[r][2]), a3 = u2f(acc[r][3]);
            float4 o0 = make_float4(a0.x, a0.y, a1.x, a1.y);
            float4 o1 = make_float4(a2.x, a2.y, a3.x, a3.y);
            *(float4*)&g_pz[ks][b][slot][et * 128 + eg * 8]     = o0;
            *(float4*)&g_pz[ks][b][slot][et * 128 + eg * 8 + 4] = o1;
        }
    }
}

// ---------------- K_attn: 2-way split-KV + last-block merge -----------------
struct AttnSmem {
    float Esh[64][260];    // door-row emb tile
    float zsh[32][260];    // z rows for this i-tile
    float ssh[64][36];     // softmax weights [j][i]
    float red[32][36];     // per-jg partial max/sum [jg][i]
    float uch[64];
    int   tj[64];
    float vch[32];
    float m[32];
    float dsum[32];
    float scale[32];
};   // ~112KB -> 2 blocks/SM

__global__ void __launch_bounds__(256, 2) k_attn(const float* __restrict__ emb,
                                                 const float* __restrict__ cwp,
                                                 float* __restrict__ out) {
    extern __shared__ char smraw[];
    AttnSmem* S = (AttnSmem*)smraw;
    const int mt = blockIdx.x, b = blockIdx.y, js = blockIdx.z;
    const int nsw = g_nsw[b];
    const int i0 = mt * 32;
    if (i0 >= nsw) return;
    const int nd = g_ndr[b];
    const int tid = threadIdx.x;
    const int ni = min(32, nsw - i0);
    const float cwv = *cwp;

    // ---- prologue: z tile (sum of K-split partials * cw), m/dsum, vc
    for (int idx = tid; idx < 32 * 64; idx += 256) {
        int i = idx >> 6, q = idx & 63;
        float4 v = make_float4(0.f, 0.f, 0.f, 0.f);
        if (i < ni) {
            float4 a = ((const float4*)&g_pz[0][b][i0 + i][0])[q];
            float4 c = ((const float4*)&g_pz[1][b][i0 + i][0])[q];
            v = make_float4(cwv * (a.x + c.x), cwv * (a.y + c.y),
                            cwv * (a.z + c.z), cwv * (a.w + c.w));
        }
        *(float4*)&S->zsh[i][q * 4] = v;
    }
    if (tid < 32) {
        S->m[tid]    = -1e30f;   // door-side max only; non-door handled in merge
        S->dsum[tid] = 0.f;
    }
    {   // vc: warp w (0..7) covers rows w, w+8, w+16, w+24
        int w = tid >> 5, lane = tid & 31;
        for (int r = w; r < 32; r += 8) {
            float val = -1e30f;
            if (r < ni) {
                int srow = g_sw_idx[b][i0 + r];
                const float4* er = (const float4*)&emb[((size_t)b * NS + srow) * ND];
                const float4* vr = (const float4*)g_vecA;
                float s = 0.f;
                #pragma unroll
                for (int j2 = 0; j2 < 2; j2++) {
                    float4 e4 = er[lane + 32 * j2], v4 = vr[lane + 32 * j2];
                    s += e4.x * v4.x + e4.y * v4.y + e4.z * v4.z + e4.w * v4.w;
                }
                #pragma unroll
                for (int o = 16; o; o >>= 1) s += __shfl_down_sync(0xFFFFFFFFu, s, o);
                val = cwv * (s + g_c);
            }
            if (lane == 0) S->vch[r] = val;
        }
    }

    // this split's door range (half)
    const int ndh = (nd + 1) >> 1;
    const int jlo = js * ndh;
    const int myn = min(nd, jlo + ndh) - jlo;   // may be <= 0

    const int ig = tid >> 5;     // 0..7  -> i = ig*4 + r
    const int jg = tid & 31;     // 0..31 -> j = jg, jg+32

    ull accv[16];
    #pragma unroll
    for (int p = 0; p < 16; p++) accv[p] = 0ULL;

    for (int jb = 0; jb < myn; jb += 64) {
        int cnt = min(64, myn - jb);
        __syncthreads();
        if (tid < 64)
            S->tj[tid] = g_dr_idx[b][jlo + ((tid < cnt) ? (jb + tid) : jb)];
        __syncthreads();
        for (int idx = tid; idx < 64 * 64; idx += 256) {
            int j = idx >> 6, q = idx & 63;
            float4 v = ((const float4*)&emb[((size_t)b * NS + S->tj[j]) * ND])[q];
            *(float4*)&S->Esh[j][q * 4] = v;
        }
        __syncthreads();
        // ---- uc_j = cw * (E_j . vecB): 4 threads per j (vecB via L1)
        {
            int j = tid >> 2, q4 = tid & 3;
            const float4* er = (const float4*)&S->Esh[j][0];
            const float4* vr = (const float4*)g_vecB;
            float s = 0.f;
            #pragma unroll
            for (int q = 0; q < 16; q++) {
                float4 e4 = er[q4 + 4 * q], v4 = vr[q4 + 4 * q];
                s += e4.x * v4.x + e4.y * v4.y + e4.z * v4.z + e4.w * v4.w;
            }
            s += __shfl_xor_sync(0xFFFFFFFFu, s, 1);
            s += __shfl_xor_sync(0xFFFFFFFFu, s, 2);
            if (q4 == 0) S->uch[j] = (j < cnt) ? cwv * s : 0.f;
        }
        __syncthreads();
        // ---- scores: thread computes 4i x 2j over full e=256
        ull sc[4][2];
        #pragma unroll
        for (int r = 0; r < 4; r++) { sc[r][0] = 0ULL; sc[r][1] = 0ULL; }
        #pragma unroll 4
        for (int e = 0; e < ND; e += 4) {
            ulonglong2 zr0 = *(const ulonglong2*)&S->zsh[ig * 4 + 0][e];
            ulonglong2 zr1 = *(const ulonglong2*)&S->zsh[ig * 4 + 1][e];
            ulonglong2 zr2 = *(const ulonglong2*)&S->zsh[ig * 4 + 2][e];
            ulonglong2 zr3 = *(const ulonglong2*)&S->zsh[ig * 4 + 3][e];
            ulonglong2 ee0 = *(const ulonglong2*)&S->Esh[jg][e];
            ulonglong2 ee1 = *(const ulonglong2*)&S->Esh[jg + 32][e];
            FMA2(sc[0][0], zr0.x, ee0.x); FMA2(sc[0][0], zr0.y, ee0.y);
            FMA2(sc[0][1], zr0.x, ee1.x); FMA2(sc[0][1], zr0.y, ee1.y);
            FMA2(sc[1][0], zr1.x, ee0.x); FMA2(sc[1][0], zr1.y, ee0.y);
            FMA2(sc[1][1], zr1.x, ee1.x); FMA2(sc[1][1], zr1.y, ee1.y);
            FMA2(sc[2][0], zr2.x, ee0.x); FMA2(sc[2][0], zr2.y, ee0.y);
            FMA2(sc[2][1], zr2.x, ee1.x); FMA2(sc[2][1], zr2.y, ee1.y);
            FMA2(sc[3][0], zr3.x, ee0.x); FMA2(sc[3][0], zr3.y, ee0.y);
            FMA2(sc[3][1], zr3.x, ee1.x); FMA2(sc[3][1], zr3.y, ee1.y);
        }
        float sv[4][2];
        #pragma unroll
        for (int r = 0; r < 4; r++) {
            float vci = S->vch[ig * 4 + r];
            float lm = -1e30f;
            #pragma unroll
            for (int c = 0; c < 2; c++) {
                int j = jg + 32 * c;
                float2 a = u2f(sc[r][c]);
                float s = (a.x + a.y) + vci + S->uch[j];
                sv[r][c] = (j < cnt) ? s : -1e30f;
                lm = fmaxf(lm, sv[r][c]);
            }
            S->red[jg][ig * 4 + r] = lm;
        }
        __syncthreads();
        if (tid < 32) {
            float mo = S->m[tid], mn = mo;
            #pragma unroll 8
            for (int g = 0; g < 32; g++) mn = fmaxf(mn, S->red[g][tid]);
            S->scale[tid] = __expf(mo - mn);
            S->m[tid] = mn;
        }
        __syncthreads();
        #pragma unroll
        for (int r = 0; r < 4; r++) {
            float mi = S->m[ig * 4 + r];
            float ls = 0.f;
            #pragma unroll
            for (int c = 0; c < 2; c++) {
                float w = __expf(sv[r][c] - mi);
                S->ssh[jg + 32 * c][ig * 4 + r] = w;
                ls += w;
            }
            S->red[jg][ig * 4 + r] = ls;
        }
        __syncthreads();
        if (tid < 32) {
            float cs = 0.f;
            #pragma unroll 8
            for (int g = 0; g < 32; g++) cs += S->red[g][tid];
            S->dsum[tid] = S->dsum[tid] * S->scale[tid] + cs;
        }
        __syncthreads();
        // ---- V accumulate: thread = d (tid), 32 i's (16 ull)
        #pragma unroll
        for (int p = 0; p < 16; p++) {
            ull sp = pack2(S->scale[2 * p], S->scale[2 * p + 1]);
            accv[p] = MUL2(accv[p], sp);
        }
        #pragma unroll 2
        for (int j = 0; j < 64; j++) {
            ull ev2 = splat2(S->Esh[j][tid]);
            ulonglong2 w0 = *(const ulonglong2*)&S->ssh[j][0];
            ulonglong2 w1 = *(const ulonglong2*)&S->ssh[j][4];
            ulonglong2 w2 = *(const ulonglong2*)&S->ssh[j][8];
            ulonglong2 w3 = *(const ulonglong2*)&S->ssh[j][12];
            ulonglong2 w4 = *(const ulonglong2*)&S->ssh[j][16];
            ulonglong2 w5 = *(const ulonglong2*)&S->ssh[j][20];
            ulonglong2 w6 = *(const ulonglong2*)&S->ssh[j][24];
            ulonglong2 w7 = *(const ulonglong2*)&S->ssh[j][28];
            FMA2(accv[0],  w0.x, ev2); FMA2(accv[1],  w0.y, ev2);
            FMA2(accv[2],  w1.x, ev2); FMA2(accv[3],  w1.y, ev2);
            FMA2(accv[4],  w2.x, ev2); FMA2(accv[5],  w2.y, ev2);
            FMA2(accv[6],  w3.x, ev2); FMA2(accv[7],  w3.y, ev2);
            FMA2(accv[8],  w4.x, ev2); FMA2(accv[9],  w4.y, ev2);
            FMA2(accv[10], w5.x, ev2); FMA2(accv[11], w5.y, ev2);
            FMA2(accv[12], w6.x, ev2); FMA2(accv[13], w6.y, ev2);
            FMA2(accv[14], w7.x, ev2); FMA2(accv[15], w7.y, ev2);
        }
    }
    __syncthreads();
    // ---- write slot-indexed partials
    if (tid < 32 && tid < ni) {
        g_pm[b][js][i0 + tid] = S->m[tid];
        g_pd[b][js][i0 + tid] = S->dsum[tid];
    }
    #pragma unroll
    for (int p = 0; p < 16; p++) {
        float2 ap = u2f(accv[p]);
        if (2 * p < ni)     g_pacc[b][js][i0 + 2 * p][tid]     = ap.x;
        if (2 * p + 1 < ni) g_pacc[b][js][i0 + 2 * p + 1][tid] = ap.y;
    }

    // ---- last-block merge (replaces k_comb)
    __threadfence();
    __syncthreads();
    __shared__ int lastFlag;
    if (tid == 0) {
        int old = atomicAdd(&g_cnt[b][mt], 1);
        lastFlag = (old == 1);
    }
    __syncthreads();
    if (!lastFlag) return;
    __threadfence();   // acquire: other split's partials now visible

    const int d = tid;
    float sndv = 0.f;
    #pragma unroll
    for (int c = 0; c < 4; c++) sndv += g_partAll[b][c][d] - g_partDoor[b][c][d];
    for (int i = 0; i < ni; i++) {
        int slot = i0 + i;
        float m0 = g_pm[b][0][slot], m1 = g_pm[b][1][slot];
        float d0 = g_pd[b][0][slot], d1 = g_pd[b][1][slot];
        float M = fmaxf(m0, m1);
        if (nd < NS) M = fmaxf(M, 0.f);
        float s0 = __expf(m0 - M), s1 = __expf(m1 - M);
        float a0 = g_pacc[b][0][slot][d], a1 = g_pacc[b][1][slot][d];
        float den = d0 * s0 + d1 * s1;
        float num = a0 * s0 + a1 * s1;
        if (nd < NS) {
            float eM = __expf(-M);
            den += (float)(NS - nd) * eM;
            num += eM * sndv;
        }
        int srow = g_sw_idx[b][slot];
        size_t o = ((size_t)b * NS + srow) * ND + d;
        out[o] = emb[o] + 0.5f * (num / den);
    }
    __syncthreads();
    if (tid == 0) g_cnt[b][mt] = 0;   // reset for next graph replay
}

// ---------------- launch: fork-join graph (all forks rejoin at the end) ------
extern "C" void kernel_launch(void* const* d_in, const int* in_sizes, int n_in,
                              void* d_out, int out_size) {
    const float* emb = (const float*)d_in[0];
    const int*   s32 = (const int*)d_in[1];   // int32 or int64, detected per block
    const float* Wq  = (const float*)d_in[2];
    const float* bq  = (const float*)d_in[3];
    const float* Wk  = (const float*)d_in[4];
    const float* bk  = (const float*)d_in[5];
    const float* cw  = (const float*)d_in[6];
    // d_in[7] = causal_bias: cancels inside softmax, unused.
    float* out = (float*)d_out;

    static bool inited = false;
    static cudaStream_t s1, s2;
    static cudaEvent_t eFork, eMask, eC, eD;
    if (!inited) {
        cudaStreamCreateWithFlags(&s1, cudaStreamNonBlocking);
        cudaStreamCreateWithFlags(&s2, cudaStreamNonBlocking);
        cudaEventCreateWithFlags(&eFork, cudaEventDisableTiming);
        cudaEventCreateWithFlags(&eMask, cudaEventDisableTiming);
        cudaEventCreateWithFlags(&eC,    cudaEventDisableTiming);
        cudaEventCreateWithFlags(&eD,    cudaEventDisableTiming);
        cudaFuncSetAttribute(k_attn, cudaFuncAttributeMaxDynamicSharedMemorySize,
                             (int)sizeof(AttnSmem));
        inited = true;
    }

    cudaEventRecord(eFork, 0);
    cudaStreamWaitEvent(s1, eFork, 0);
    cudaStreamWaitEvent(s2, eFork, 0);

    // launch 1-3: k_M (main) || k_masks -> k_colsum (s1)
    k_M<<<65, 256>>>(Wq, Wk, bq, bk);
    k_masks<<<NB, 1024, 0, s1>>>(s32);
    cudaEventRecord(eMask, s1);
    k_colsum<<<dim3(NB, 4), 1024, 0, s1>>>(s32, emb);
    cudaEventRecord(eC, s1);

    // launch 4: k_z (main; needs M + masks) — ncu profiles this
    cudaStreamWaitEvent(0, eMask, 0);
    k_z<<<dim3(2, NB, 32), 256>>>(emb);

    // launch 5: k_attn 2-way split-KV + merge (main; needs z + colsum)
    cudaStreamWaitEvent(0, eC, 0);
    k_attn<<<dim3(NS / 32, NB, 2), 256, sizeof(AttnSmem)>>>(emb, cw, out);

    // launch 6: k_default (s2; needs masks + colsum; row-disjoint with k_attn)
    cudaStreamWaitEvent(s2, eC, 0);
    k_default<<<(NB * NS * (ND / 4)) / 256, 256, 0, s2>>>(emb, out);
    cudaEventRecord(eD, s2);
    cudaStreamWaitEvent(0, eD, 0);
}